// round 3
// baseline (speedup 1.0000x reference)
#include <cuda_runtime.h>

#define N_NODES 100000
#define N_EDGES 1600000
#define NFEAT   48
#define HIDDEN  256

// Scratch (no allocation allowed -> __device__ globals)
__device__ float g_w[NFEAT];     // fused W1@W2
__device__ float g_c;            // fused bias term
__device__ float g_deg[N_NODES]; // degree (incl. self loop)
__device__ float g_dinv[N_NODES];
__device__ float g_z[N_NODES];   // (x[i] . w) * dinv[i]

// ---- 1. fuse weights: w[f] = sum_h W1[f,h]*W2[h];  c = bias*sum(W2)+b2 ----
__global__ void k_fuse_w(const float* __restrict__ W1,
                         const float* __restrict__ bias,
                         const float* __restrict__ W2,
                         const float* __restrict__ b2) {
    __shared__ float s_w2[HIDDEN];
    int t = threadIdx.x;
    s_w2[t] = W2[t];
    __syncthreads();
    if (t < NFEAT) {
        const float* r = W1 + t * HIDDEN;
        float acc = 0.f;
#pragma unroll 8
        for (int h = 0; h < HIDDEN; ++h) acc = fmaf(r[h], s_w2[h], acc);
        g_w[t] = acc;
    }
    if (t == 0) {
        float s = 0.f;
        for (int h = 0; h < HIDDEN; ++h) s += s_w2[h];
        g_c = bias[0] * s + b2[0];
    }
}

// ---- 2. init degree = 1 (self loop) ----
__global__ void k_init_deg() {
    int i = blockIdx.x * blockDim.x + threadIdx.x;
    if (i < N_NODES) g_deg[i] = 1.0f;
}

// ---- 3. count degree over edges ----
__global__ void k_count_deg(const int* __restrict__ ei) {
    int e = blockIdx.x * blockDim.x + threadIdx.x;
    if (e < N_EDGES) {
        int col = ei[N_EDGES + e];  // destination
        atomicAdd(&g_deg[col], 1.0f);
    }
}

// ---- 4. per-node: dinv, z = (x.w)*dinv, out = z (self-loop term) ----
__global__ void k_node(const float* __restrict__ x, float* __restrict__ out) {
    int i = blockIdx.x * blockDim.x + threadIdx.x;
    if (i >= N_NODES) return;

    float dinv = rsqrtf(g_deg[i]);   // deg >= 1 always
    const float4* xr = reinterpret_cast<const float4*>(x + (size_t)i * NFEAT);
    const float4* wv = reinterpret_cast<const float4*>(g_w);

    float acc = 0.f;
#pragma unroll
    for (int j = 0; j < NFEAT / 4; ++j) {
        float4 a = __ldg(&xr[j]);
        float4 b = wv[j];
        acc = fmaf(a.x, b.x, acc);
        acc = fmaf(a.y, b.y, acc);
        acc = fmaf(a.z, b.z, acc);
        acc = fmaf(a.w, b.w, acc);
    }
    float z = acc * dinv;
    g_dinv[i] = dinv;
    g_z[i]    = z;
    out[i]    = z;   // self-loop contribution: dinv applied again in finalize
}

// ---- 5. scatter: out[col] += z[row] ----
__global__ void k_scatter(const int* __restrict__ ei, float* __restrict__ out) {
    int e = blockIdx.x * blockDim.x + threadIdx.x;
    if (e < N_EDGES) {
        int row = ei[e];             // source
        int col = ei[N_EDGES + e];   // destination
        atomicAdd(&out[col], __ldg(&g_z[row]));
    }
}

// ---- 6. finalize: out = out*dinv + c ----
__global__ void k_final(float* __restrict__ out) {
    int i = blockIdx.x * blockDim.x + threadIdx.x;
    if (i < N_NODES) out[i] = fmaf(out[i], g_dinv[i], g_c);
}

extern "C" void kernel_launch(void* const* d_in, const int* in_sizes, int n_in,
                              void* d_out, int out_size) {
    const float* x    = (const float*)d_in[0];
    const int*   ei   = (const int*)  d_in[1];
    const float* W1   = (const float*)d_in[2];
    const float* bias = (const float*)d_in[3];
    const float* W2   = (const float*)d_in[4];
    const float* b2   = (const float*)d_in[5];
    float* out = (float*)d_out;

    const int TB = 256;
    const int nb_nodes = (N_NODES + TB - 1) / TB;
    const int nb_edges = (N_EDGES + TB - 1) / TB;

    k_fuse_w   <<<1, HIDDEN>>>(W1, bias, W2, b2);
    k_init_deg <<<nb_nodes, TB>>>();
    k_count_deg<<<nb_edges, TB>>>(ei);
    k_node     <<<nb_nodes, TB>>>(x, out);
    k_scatter  <<<nb_edges, TB>>>(ei, out);
    k_final    <<<nb_nodes, TB>>>(out);
}